// round 3
// baseline (speedup 1.0000x reference)
#include <cuda_runtime.h>
#include <cuda_bf16.h>

#define NN   30000
#define EE   960000
#define HID  128
#define LL   3
#define BB   64
#define NSHARD 8

// ---------------- device scratch ----------------
__device__ __align__(16) float  g_h[NN * HID];
__device__ __align__(16) float  g_xl[NN * HID];
__device__ __align__(16) float  g_xr[NN * HID];
__device__ __align__(16) float  g_g[NN * HID];
__device__ __align__(16) int    g_cnt[32768];          // padded for int4 scan
__device__ int    g_rowptr[NN + 1];
__device__ int    g_fill[NN];
__device__ __align__(16) float4 g_csr[EE];
__device__ __align__(16) float  g_M[LL * 4 * HID];     // {ea0,ea1,ea2,const} per layer
__device__ __align__(16) float  g_bnsum[NSHARD * HID];
__device__ __align__(16) float  g_bnsq[NSHARD * HID];
__device__ __align__(16) float  g_z1[BB * 256];
__device__ __align__(16) float  g_z2[BB * 128];

// ---------------- h = x @ npW + npB; also zero g_cnt / g_fill ----------------
__global__ void k_node_proj(const float* __restrict__ x,
                            const float* __restrict__ npW,
                            const float* __restrict__ npB)
{
    __shared__ float Ws[28 * HID];
    int tid = threadIdx.x;                    // 128
    int gtid = blockIdx.x * 128 + tid;
    if (gtid < 32768) g_cnt[gtid] = 0;
    else if (gtid < 32768 + NN) g_fill[gtid - 32768] = 0;

    for (int i = tid; i < 28 * HID; i += 128) Ws[i] = npW[i];
    __syncthreads();
    float bias = npB[tid];
    int row0 = blockIdx.x * 32;
    for (int r = 0; r < 32; r++) {
        int row = row0 + r;
        if (row >= NN) break;
        const float* xr = x + row * 28;
        float acc = bias;
        #pragma unroll
        for (int k = 0; k < 28; k++) acc = fmaf(__ldg(xr + k), Ws[k * HID + tid], acc);
        g_h[row * HID + tid] = acc;
    }
}

// ---------------- M[l] = epW @ We[l], const row = epB @ We[l] ----------------
__global__ void k_precM(const float* __restrict__ epW,
                        const float* __restrict__ epB,
                        const float* __restrict__ We)
{
    int c = threadIdx.x;                      // 128
    for (int l = 0; l < LL; l++) {
        const float* W = We + l * HID * HID;
        float m0 = 0.f, m1 = 0.f, m2 = 0.f, mc = 0.f;
        for (int k = 0; k < HID; k++) {
            float w = W[k * HID + c];
            m0 = fmaf(epW[0 * HID + k], w, m0);
            m1 = fmaf(epW[1 * HID + k], w, m1);
            m2 = fmaf(epW[2 * HID + k], w, m2);
            mc = fmaf(epB[k], w, mc);
        }
        g_M[l * 512 + 0 * HID + c] = m0;
        g_M[l * 512 + 1 * HID + c] = m1;
        g_M[l * 512 + 2 * HID + c] = m2;
        g_M[l * 512 + 3 * HID + c] = mc;
    }
}

// ---------------- degree histogram ----------------
__global__ void k_deg(const int* __restrict__ ei)
{
    int e = blockIdx.x * blockDim.x + threadIdx.x;
    if (e >= EE) return;
    atomicAdd(&g_cnt[ei[EE + e]], 1);
}

// ---------------- exclusive scan (single block, smem-staged coalesced out) ----------------
__global__ void k_scan()
{
    extern __shared__ int sst[];
    int* stage = sst;                         // 33792 ints (padded i + i/32)
    int* part  = sst + 33792;                 // 1024 ints
    int t = threadIdx.x;
    int base = t * 32;
    int vals[32];
    const int4* c4 = (const int4*)&g_cnt[base];
    int s = 0;
    #pragma unroll
    for (int q = 0; q < 8; q++) {
        int4 v = c4[q];
        vals[q * 4 + 0] = v.x; vals[q * 4 + 1] = v.y;
        vals[q * 4 + 2] = v.z; vals[q * 4 + 3] = v.w;
        s += v.x + v.y + v.z + v.w;
    }
    part[t] = s;
    __syncthreads();
    for (int off = 1; off < 1024; off <<= 1) {
        int v = (t >= off) ? part[t - off] : 0;
        __syncthreads();
        part[t] += v;
        __syncthreads();
    }
    int run = (t == 0) ? 0 : part[t - 1];
    #pragma unroll
    for (int q = 0; q < 32; q++) {
        int i = base + q;
        stage[i + (i >> 5)] = run;            // bank = (t+q)%32, conflict-free
        run += vals[q];
    }
    __syncthreads();
    for (int i = t; i <= NN; i += 1024)
        g_rowptr[i] = stage[i + (i >> 5)];
}

// ---------------- scatter edges into CSR ----------------
__global__ void k_scatter(const int* __restrict__ ei, const float* __restrict__ ea)
{
    int e = blockIdx.x * blockDim.x + threadIdx.x;
    if (e >= EE) return;
    int s = ei[e];
    int d = ei[EE + e];
    int pos = g_rowptr[d] + atomicAdd(&g_fill[d], 1);
    g_csr[pos] = make_float4(__int_as_float(s), ea[e * 3 + 0], ea[e * 3 + 1], ea[e * 3 + 2]);
}

// ---------------- fused xl/xr GEMM: 64x256 tile, 256 threads ----------------
__global__ void __launch_bounds__(256)
k_gemm2(const float* __restrict__ W0, const float* __restrict__ b0,
        const float* __restrict__ W1, const float* __restrict__ b1)
{
    __shared__ __align__(16) float As[32][68];    // k-major transposed A
    __shared__ __align__(16) float Bs[32][260];   // cols 0-127 = W0, 128-255 = W1
    int tid = threadIdx.x;
    int tx = tid & 31;                        // 32 col groups of 4
    int ty = tid >> 5;                        // 8 row groups of 8
    int row0 = blockIdx.x * 64;

    if (blockIdx.x == 0) {                    // zero bn shard accumulators
        for (int i = tid; i < NSHARD * HID; i += 256) {
            g_bnsum[i] = 0.f; g_bnsq[i] = 0.f;
        }
    }

    float acc[8][8];
    {
        float4 c0 = *(const float4*)&b0[tx * 4];
        float4 c1 = *(const float4*)&b1[tx * 4];
        #pragma unroll
        for (int i = 0; i < 8; i++) {
            acc[i][0] = c0.x; acc[i][1] = c0.y; acc[i][2] = c0.z; acc[i][3] = c0.w;
            acc[i][4] = c1.x; acc[i][5] = c1.y; acc[i][6] = c1.z; acc[i][7] = c1.w;
        }
    }

    for (int kb = 0; kb < HID; kb += 32) {
        #pragma unroll
        for (int q = 0; q < 2; q++) {          // A: 64 rows x 32 k = 512 float4
            int idx = tid + q * 256;
            int r = idx >> 3;
            int kk = (idx & 7) << 2;
            int row = row0 + r; if (row >= NN) row = NN - 1;
            float4 v = *(const float4*)&g_h[row * HID + kb + kk];
            As[kk + 0][r] = v.x; As[kk + 1][r] = v.y;
            As[kk + 2][r] = v.z; As[kk + 3][r] = v.w;
        }
        #pragma unroll
        for (int q = 0; q < 8; q++) {          // B: 32 k x 256 = 2048 float4
            int idx = tid + q * 256;
            int kk = idx >> 6;
            int c4 = (idx & 63) << 2;
            const float* src = (c4 < 128) ? &W0[(kb + kk) * HID + c4]
                                          : &W1[(kb + kk) * HID + (c4 - 128)];
            *(float4*)&Bs[kk][c4] = *(const float4*)src;
        }
        __syncthreads();
        #pragma unroll
        for (int k = 0; k < 32; k++) {
            float4 a0 = *(const float4*)&As[k][ty * 8];
            float4 a1 = *(const float4*)&As[k][ty * 8 + 4];
            float4 q0 = *(const float4*)&Bs[k][tx * 4];
            float4 q1 = *(const float4*)&Bs[k][128 + tx * 4];
            float a[8] = {a0.x, a0.y, a0.z, a0.w, a1.x, a1.y, a1.z, a1.w};
            float b[8] = {q0.x, q0.y, q0.z, q0.w, q1.x, q1.y, q1.z, q1.w};
            #pragma unroll
            for (int i = 0; i < 8; i++)
                #pragma unroll
                for (int j = 0; j < 8; j++)
                    acc[i][j] = fmaf(a[i], b[j], acc[i][j]);
        }
        __syncthreads();
    }
    #pragma unroll
    for (int i = 0; i < 8; i++) {
        int row = row0 + ty * 8 + i;
        if (row < NN) {
            *(float4*)&g_xl[row * HID + tx * 4] =
                make_float4(acc[i][0], acc[i][1], acc[i][2], acc[i][3]);
            *(float4*)&g_xr[row * HID + tx * 4] =
                make_float4(acc[i][4], acc[i][5], acc[i][6], acc[i][7]);
        }
    }
}

// ---------------- GATv2 + fused BN stats: one warp per dst ----------------
__global__ void __launch_bounds__(256)
k_gat(const float* __restrict__ att, const float* __restrict__ gbias, int layer)
{
    __shared__ __align__(16) float s_o[8][128];
    int warp = threadIdx.x >> 5;
    int lane = threadIdx.x & 31;
    int v = blockIdx.x * 8 + warp;            // 3750*8 == NN exactly

    const float* Mb = g_M + layer * 512;
    float4 M0 = *(const float4*)(Mb + 0 * HID + lane * 4);
    float4 M1 = *(const float4*)(Mb + 1 * HID + lane * 4);
    float4 M2 = *(const float4*)(Mb + 2 * HID + lane * 4);
    float4 MC = *(const float4*)(Mb + 3 * HID + lane * 4);
    float4 av = *(const float4*)(att + layer * HID + lane * 4);
    const float LOG2E = 1.44269504088896f;
    av.x *= LOG2E; av.y *= LOG2E; av.z *= LOG2E; av.w *= LOG2E;
    float4 xr4 = *(const float4*)(g_xr + (size_t)v * HID + lane * 4);
    float4 base = make_float4(xr4.x + MC.x, xr4.y + MC.y, xr4.z + MC.z, xr4.w + MC.w);

    float den = 0.f;
    float4 acc = make_float4(0.f, 0.f, 0.f, 0.f);
    float sa0 = 0.f, sa1 = 0.f, sa2 = 0.f;

    int e0 = g_rowptr[v], e1 = g_rowptr[v + 1];
    float4 ed = make_float4(0.f, 0.f, 0.f, 0.f);
    float4 xs = make_float4(0.f, 0.f, 0.f, 0.f);
    if (e0 < e1) {
        ed = __ldg(&g_csr[e0]);
        xs = *(const float4*)(g_xl + (size_t)__float_as_int(ed.x) * HID + lane * 4);
    }
    for (int e = e0; e < e1; e++) {
        float4 edc = ed;
        float4 xsc = xs;
        if (e + 1 < e1) {
            ed = __ldg(&g_csr[e + 1]);
            xs = *(const float4*)(g_xl + (size_t)__float_as_int(ed.x) * HID + lane * 4);
        }
        sa0 += edc.y; sa1 += edc.z; sa2 += edc.w;
        float t0 = xsc.x + fmaf(edc.y, M0.x, fmaf(edc.z, M1.x, fmaf(edc.w, M2.x, base.x)));
        float t1 = xsc.y + fmaf(edc.y, M0.y, fmaf(edc.z, M1.y, fmaf(edc.w, M2.y, base.y)));
        float t2 = xsc.z + fmaf(edc.y, M0.z, fmaf(edc.z, M1.z, fmaf(edc.w, M2.z, base.z)));
        float t3 = xsc.w + fmaf(edc.y, M0.w, fmaf(edc.z, M1.w, fmaf(edc.w, M2.w, base.w)));
        t0 = fmaxf(t0, 0.2f * t0);
        t1 = fmaxf(t1, 0.2f * t1);
        t2 = fmaxf(t2, 0.2f * t2);
        t3 = fmaxf(t3, 0.2f * t3);
        float p = fmaf(t0, av.x, fmaf(t1, av.y, fmaf(t2, av.z, t3 * av.w)));
        p += __shfl_xor_sync(0xffffffffu, p, 1);
        p += __shfl_xor_sync(0xffffffffu, p, 2);
        p += __shfl_xor_sync(0xffffffffu, p, 4);      // per-head sum (8 lanes)
        float f = exp2f(p);
        den += f;
        acc.x = fmaf(f, xsc.x, acc.x);
        acc.y = fmaf(f, xsc.y, acc.y);
        acc.z = fmaf(f, xsc.z, acc.z);
        acc.w = fmaf(f, xsc.w, acc.w);
    }
    // self loop (edge feature = mean of incoming projected attrs)
    {
        int cnt = e1 - e0;
        float rc = 1.0f / fmaxf((float)cnt, 1.0f);
        float a0 = sa0 * rc, a1 = sa1 * rc, a2 = sa2 * rc;
        float aCm1 = (cnt > 0) ? 0.0f : -1.0f;        // aC - 1
        float4 xv = *(const float4*)(g_xl + (size_t)v * HID + lane * 4);
        float t0 = xv.x + fmaf(a0, M0.x, fmaf(a1, M1.x, fmaf(a2, M2.x, fmaf(aCm1, MC.x, base.x))));
        float t1 = xv.y + fmaf(a0, M0.y, fmaf(a1, M1.y, fmaf(a2, M2.y, fmaf(aCm1, MC.y, base.y))));
        float t2 = xv.z + fmaf(a0, M0.z, fmaf(a1, M1.z, fmaf(a2, M2.z, fmaf(aCm1, MC.z, base.z))));
        float t3 = xv.w + fmaf(a0, M0.w, fmaf(a1, M1.w, fmaf(a2, M2.w, fmaf(aCm1, MC.w, base.w))));
        t0 = fmaxf(t0, 0.2f * t0);
        t1 = fmaxf(t1, 0.2f * t1);
        t2 = fmaxf(t2, 0.2f * t2);
        t3 = fmaxf(t3, 0.2f * t3);
        float p = fmaf(t0, av.x, fmaf(t1, av.y, fmaf(t2, av.z, t3 * av.w)));
        p += __shfl_xor_sync(0xffffffffu, p, 1);
        p += __shfl_xor_sync(0xffffffffu, p, 2);
        p += __shfl_xor_sync(0xffffffffu, p, 4);
        float f = exp2f(p);
        den += f;
        acc.x = fmaf(f, xv.x, acc.x);
        acc.y = fmaf(f, xv.y, acc.y);
        acc.z = fmaf(f, xv.z, acc.z);
        acc.w = fmaf(f, xv.w, acc.w);
    }
    float inv = 1.0f / (den + 1e-16f);
    float4 gb = *(const float4*)(gbias + layer * HID + lane * 4);
    float4 o = make_float4(fmaf(acc.x, inv, gb.x), fmaf(acc.y, inv, gb.y),
                           fmaf(acc.z, inv, gb.z), fmaf(acc.w, inv, gb.w));
    *(float4*)(g_g + (size_t)v * HID + lane * 4) = o;

    // fused BN statistics: block reduce then sharded atomics
    *(float4*)&s_o[warp][lane * 4] = o;
    __syncthreads();
    int t = threadIdx.x;
    if (t < 128) {
        float s = 0.f, s2 = 0.f;
        #pragma unroll
        for (int w = 0; w < 8; w++) {
            float vv = s_o[w][t];
            s += vv; s2 = fmaf(vv, vv, s2);
        }
        int shard = (blockIdx.x & (NSHARD - 1)) * HID + t;
        atomicAdd(&g_bnsum[shard], s);
        atomicAdd(&g_bnsq[shard], s2);
    }
}

// ---------------- h = relu(bn(g)) + h (float4, shard-summing) ----------------
__global__ void k_bnapply(const float* __restrict__ bng, const float* __restrict__ bnb, int layer)
{
    int idx = blockIdx.x * blockDim.x + threadIdx.x;   // over NN*HID/4
    if (idx >= NN * HID / 4) return;
    int cq = idx & 31;                                 // float4 channel group
    float4 sum = make_float4(0.f, 0.f, 0.f, 0.f);
    float4 sq  = make_float4(0.f, 0.f, 0.f, 0.f);
    #pragma unroll
    for (int s = 0; s < NSHARD; s++) {
        float4 a = ((const float4*)g_bnsum)[s * 32 + cq];
        float4 b = ((const float4*)g_bnsq)[s * 32 + cq];
        sum.x += a.x; sum.y += a.y; sum.z += a.z; sum.w += a.w;
        sq.x += b.x; sq.y += b.y; sq.z += b.z; sq.w += b.w;
    }
    int cg = cq * 4;
    const float invN = 1.0f / NN;
    float4 gm = *(const float4*)&bng[layer * HID + cg];
    float4 bt = *(const float4*)&bnb[layer * HID + cg];
    float m0 = sum.x * invN, m1 = sum.y * invN, m2 = sum.z * invN, m3 = sum.w * invN;
    float r0 = rsqrtf(sq.x * invN - m0 * m0 + 1e-5f) * gm.x;
    float r1 = rsqrtf(sq.y * invN - m1 * m1 + 1e-5f) * gm.y;
    float r2 = rsqrtf(sq.z * invN - m2 * m2 + 1e-5f) * gm.z;
    float r3 = rsqrtf(sq.w * invN - m3 * m3 + 1e-5f) * gm.w;
    float4 g4 = *(const float4*)&g_g[idx * 4];
    float4 h4 = *(const float4*)&g_h[idx * 4];
    h4.x += fmaxf(fmaf(g4.x - m0, r0, bt.x), 0.f);
    h4.y += fmaxf(fmaf(g4.y - m1, r1, bt.y), 0.f);
    h4.z += fmaxf(fmaf(g4.z - m2, r2, bt.z), 0.f);
    h4.w += fmaxf(fmaf(g4.w - m3, r3, bt.w), 0.f);
    *(float4*)&g_h[idx * 4] = h4;
}

// ---------------- head: z1 = comb @ r1W + r1b ----------------
__global__ void __launch_bounds__(256)
k_head1(const int* __restrict__ mut, const float* __restrict__ pert,
        const float* __restrict__ r1W, const float* __restrict__ r1b)
{
    __shared__ float comb[64 * 140];
    __shared__ float Ws[137 * 16];
    int tid = threadIdx.x;
    int colbase = blockIdx.x * 16;
    for (int i = tid; i < 64 * 137; i += 256) {
        int b = i / 137, k = i - b * 137;
        float vv = (k < HID) ? g_h[(size_t)mut[b] * HID + k] : pert[b * 9 + (k - HID)];
        comb[b * 140 + k] = vv;
    }
    for (int i = tid; i < 137 * 16; i += 256) {
        int k = i >> 4, c = i & 15;
        Ws[k * 16 + c] = r1W[k * 256 + colbase + c];
    }
    __syncthreads();
    int row = tid >> 2;
    int cq = (tid & 3) * 4;
    float4 accv = *(const float4*)&r1b[colbase + cq];
    for (int k = 0; k < 137; k++) {
        float a = comb[row * 140 + k];
        float4 w = *(const float4*)&Ws[k * 16 + cq];
        accv.x = fmaf(a, w.x, accv.x);
        accv.y = fmaf(a, w.y, accv.y);
        accv.z = fmaf(a, w.z, accv.z);
        accv.w = fmaf(a, w.w, accv.w);
    }
    *(float4*)&g_z1[row * 256 + colbase + cq] = accv;
}

// ---------------- head BN+relu over 64 rows ----------------
__global__ void k_bnrelu_head(float* __restrict__ z, const float* __restrict__ g,
                              const float* __restrict__ b, int cols)
{
    int c = threadIdx.x;
    if (c >= cols) return;
    float s = 0.f, s2 = 0.f;
    for (int r = 0; r < 64; r++) {
        float v = z[r * cols + c];
        s += v; s2 = fmaf(v, v, s2);
    }
    float m = s * (1.f / 64), var = s2 * (1.f / 64) - m * m;
    float rs = rsqrtf(var + 1e-5f) * g[c];
    float bt = b[c];
    for (int r = 0; r < 64; r++)
        z[r * cols + c] = fmaxf(fmaf(z[r * cols + c] - m, rs, bt), 0.f);
}

// ---------------- head: z2 = z1 @ r2W + r2b ----------------
__global__ void __launch_bounds__(256)
k_head2(const float* __restrict__ r2W, const float* __restrict__ r2b)
{
    extern __shared__ float sm[];
    float* z1s = sm;                  // 64 * 260
    float* Ws  = sm + 64 * 260;       // 256 * 16
    int tid = threadIdx.x;
    int colbase = blockIdx.x * 16;
    for (int i = tid; i < 64 * 64; i += 256) {
        int r = i >> 6;
        int kq = (i & 63) * 4;
        *(float4*)&z1s[r * 260 + kq] = *(const float4*)&g_z1[r * 256 + kq];
    }
    for (int i = tid; i < 256 * 16; i += 256) {
        int k = i >> 4, c = i & 15;
        Ws[k * 16 + c] = r2W[k * 128 + colbase + c];
    }
    __syncthreads();
    int row = tid >> 2;
    int cq = (tid & 3) * 4;
    float4 accv = *(const float4*)&r2b[colbase + cq];
    for (int k = 0; k < 256; k++) {
        float a = z1s[row * 260 + k];
        float4 w = *(const float4*)&Ws[k * 16 + cq];
        accv.x = fmaf(a, w.x, accv.x);
        accv.y = fmaf(a, w.y, accv.y);
        accv.z = fmaf(a, w.z, accv.z);
        accv.w = fmaf(a, w.w, accv.w);
    }
    *(float4*)&g_z2[row * 128 + colbase + cq] = accv;
}

// ---------------- head: z3 = relu(z2 @ r3W + r3b); outputs ----------------
__global__ void __launch_bounds__(256)
k_head3(const float* __restrict__ r3W, const float* __restrict__ r3b,
        const float* __restrict__ clsW, const float* __restrict__ clsb,
        const float* __restrict__ regW, const float* __restrict__ regb,
        float* __restrict__ out)
{
    extern __shared__ float sm[];
    float* z2s = sm;                  // 64 * 132
    float* Ws  = sm + 64 * 132;       // 128 * 64
    float* z3  = Ws + 128 * 64;       // 64 * 68
    int tid = threadIdx.x;
    for (int i = tid; i < 64 * 32; i += 256) {
        int r = i >> 5;
        int kq = (i & 31) * 4;
        *(float4*)&z2s[r * 132 + kq] = *(const float4*)&g_z2[r * 128 + kq];
    }
    for (int i = tid; i < 128 * 16; i += 256) {
        int idx4 = i * 4;
        *(float4*)&Ws[idx4] = *(const float4*)&r3W[idx4];
    }
    __syncthreads();
    int row = tid >> 2;
    int cg = (tid & 3) * 16;
    float acc[16];
    #pragma unroll
    for (int j = 0; j < 16; j++) acc[j] = r3b[cg + j];
    for (int k = 0; k < 128; k++) {
        float a = z2s[row * 132 + k];
        #pragma unroll
        for (int j = 0; j < 16; j++)
            acc[j] = fmaf(a, Ws[k * 64 + cg + j], acc[j]);
    }
    #pragma unroll
    for (int j = 0; j < 16; j++) z3[row * 68 + cg + j] = fmaxf(acc[j], 0.f);
    __syncthreads();
    if (tid < 64) {
        int b = tid;
        float c1 = clsb[0], c2 = regb[0];
        for (int k = 0; k < 64; k++) {
            float v = z3[b * 68 + k];
            c1 = fmaf(v, clsW[k], c1);
            c2 = fmaf(v, regW[k], c2);
        }
        out[b * 2 + 0] = c1;
        out[b * 2 + 1] = c2;
    }
}

// ---------------- launch ----------------
extern "C" void kernel_launch(void* const* d_in, const int* in_sizes, int n_in,
                              void* d_out, int out_size)
{
    (void)in_sizes; (void)n_in; (void)out_size;
    const float* x     = (const float*)d_in[0];
    const float* eattr = (const float*)d_in[1];
    const int*   eidx  = (const int*)d_in[2];
    const int*   mut   = (const int*)d_in[3];
    const float* pert  = (const float*)d_in[4];
    const float* npW   = (const float*)d_in[5];
    const float* npB   = (const float*)d_in[6];
    const float* epW   = (const float*)d_in[7];
    const float* epB   = (const float*)d_in[8];
    const float* Wl    = (const float*)d_in[9];
    const float* bl    = (const float*)d_in[10];
    const float* Wr    = (const float*)d_in[11];
    const float* br    = (const float*)d_in[12];
    const float* We    = (const float*)d_in[13];
    const float* att   = (const float*)d_in[14];
    const float* gbias = (const float*)d_in[15];
    const float* bng   = (const float*)d_in[16];
    const float* bnb   = (const float*)d_in[17];
    const float* r1W   = (const float*)d_in[18];
    const float* r1b   = (const float*)d_in[19];
    const float* bn1g  = (const float*)d_in[20];
    const float* bn1b  = (const float*)d_in[21];
    const float* r2W   = (const float*)d_in[22];
    const float* r2b   = (const float*)d_in[23];
    const float* bn2g  = (const float*)d_in[24];
    const float* bn2b  = (const float*)d_in[25];
    const float* r3W   = (const float*)d_in[26];
    const float* r3b   = (const float*)d_in[27];
    const float* clsW  = (const float*)d_in[28];
    const float* clsb  = (const float*)d_in[29];
    const float* regW  = (const float*)d_in[30];
    const float* regb  = (const float*)d_in[31];
    float* out = (float*)d_out;

    void *p_z1, *p_z2;
    cudaGetSymbolAddress(&p_z1, g_z1);
    cudaGetSymbolAddress(&p_z2, g_z2);

    k_node_proj<<<(NN + 31) / 32, 128>>>(x, npW, npB);
    k_precM<<<1, 128>>>(epW, epB, We);
    k_deg<<<(EE + 255) / 256, 256>>>(eidx);
    size_t scan_smem = (33792 + 1024) * sizeof(int);
    cudaFuncSetAttribute(k_scan, cudaFuncAttributeMaxDynamicSharedMemorySize, (int)scan_smem);
    k_scan<<<1, 1024, scan_smem>>>();
    k_scatter<<<(EE + 255) / 256, 256>>>(eidx, eattr);

    for (int l = 0; l < LL; l++) {
        k_gemm2<<<(NN + 63) / 64, 256>>>(
            Wl + (size_t)l * HID * HID, bl + l * HID,
            Wr + (size_t)l * HID * HID, br + l * HID);
        k_gat<<<NN / 8, 256>>>(att, gbias, l);
        k_bnapply<<<(NN * HID / 4 + 255) / 256, 256>>>(bng, bnb, l);
    }

    k_head1<<<16, 256>>>(mut, pert, r1W, r1b);
    k_bnrelu_head<<<1, 256>>>((float*)p_z1, bn1g, bn1b, 256);
    size_t smem2 = (64 * 260 + 256 * 16) * sizeof(float);
    cudaFuncSetAttribute(k_head2, cudaFuncAttributeMaxDynamicSharedMemorySize, (int)smem2);
    k_head2<<<8, 256, smem2>>>(r2W, r2b);
    k_bnrelu_head<<<1, 128>>>((float*)p_z2, bn2g, bn2b, 128);
    size_t smem3 = (64 * 132 + 128 * 64 + 64 * 68) * sizeof(float);
    cudaFuncSetAttribute(k_head3, cudaFuncAttributeMaxDynamicSharedMemorySize, (int)smem3);
    k_head3<<<1, 256, smem3>>>(r3W, r3b, clsW, clsb, regW, regb, out);
}